// round 10
// baseline (speedup 1.0000x reference)
#include <cuda_runtime.h>
#include <math.h>

// Problem constants: B=32, C=3, H=W=512
#define BB 32
#define CC 3
#define HH 512
#define WW 512
#define PX 4   // pixels per thread, warp-interleaved (stride 32)

// Fused kernel. Warp-interleaved mapping; bilinear gathers use aligned float2
// x-pair loads (even lanes: one LDG.64 covers both x-corners; odd lanes add one
// exact scalar LDG.32). Forced to 32 regs / 8 CTAs per SM.
__global__ __launch_bounds__(256, 8) void warp_kernel(const float* __restrict__ x,
                                                      const float* __restrict__ thetas,
                                                      const float* __restrict__ l1s,
                                                      const float* __restrict__ l2s,
                                                      float* __restrict__ out) {
    int lane = threadIdx.x;                           // 0..31
    int py   = blockIdx.y * blockDim.y + threadIdx.y;
    int b    = blockIdx.z;
    int px0  = blockIdx.x * (32 * PX) + lane;

    // theta matrix (translation exactly zero); uniform within the CTA
    float th = -__ldg(thetas + b);
    float c, s;
    __sincosf(th, &s, &c);
    float il1 = 1.0f / __ldg(l1s + b);
    float il2 = 1.0f / __ldg(l2s + b);
    float m00 = c * c * il1 + s * s * il2;
    float m11 = s * s * il1 + c * c * il2;
    float m01 = c * s * (il2 - il1);

    float X = ((float)px0 + 0.5f) * (2.0f / (float)WW) - 1.0f;
    float Y = ((float)py + 0.5f) * (2.0f / (float)HH) - 1.0f;

    float gx = (m00 * X + m01 * Y + 1.0f) * ((float)WW * 0.5f) - 0.5f;
    float gy = (m01 * X + m11 * Y + 1.0f) * ((float)HH * 0.5f) - 0.5f;
    float sx = 32.0f * m00;
    float sy = 32.0f * m01;

    const float* p0 = x + (size_t)b * CC * HH * WW;
    float* ob = out + ((size_t)b * CC) * HH * WW + (size_t)py * WW + px0;

#pragma unroll
    for (int k = 0; k < PX; k++) {
        float x0f = floorf(gx);
        float y0f = floorf(gy);
        int x0 = (int)x0f;
        int y0 = (int)y0f;

        float wx1 = gx - x0f;
        float wx0 = 1.0f - wx1;
        float wy1 = gy - y0f;
        float wy0 = 1.0f - wy1;

        // fold border masks into the 1D weights
        float cx0 = ((unsigned)x0       < (unsigned)WW) ? wx0 : 0.0f;
        float cx1 = ((unsigned)(x0 + 1) < (unsigned)WW) ? wx1 : 0.0f;
        float cy0 = ((unsigned)y0       < (unsigned)HH) ? wy0 : 0.0f;
        float cy1 = ((unsigned)(y0 + 1) < (unsigned)HH) ? wy1 : 0.0f;

        float w00 = cy0 * cx0;
        float w01 = cy0 * cx1;
        float w10 = cy1 * cx0;
        float w11 = cy1 * cx1;

        int par = x0 & 1;                 // x-parity of the left corner
        int e0  = y0 * WW + x0 - par;     // even (8B-aligned) base index, row y0

        // f-load needed: par==0 -> any of (x0,x1) used; par==1 -> x0 used.
        bool f0 = par ? (w00 != 0.0f) : (w00 != 0.0f || w01 != 0.0f);
        bool g0 = (par != 0) && (w01 != 0.0f);     // scalar x1 load, row y0
        bool f1 = par ? (w10 != 0.0f) : (w10 != 0.0f || w11 != 0.0f);
        bool g1 = (par != 0) && (w11 != 0.0f);     // scalar x1 load, row y1

#pragma unroll
        for (int cc = 0; cc < CC; cc++) {
            const float* p = p0 + cc * (HH * WW);
            float2 a0 = make_float2(0.f, 0.f);
            float2 b0q = make_float2(0.f, 0.f);
            float  s0 = 0.f, s1 = 0.f;
            if (f0) a0  = __ldg((const float2*)(p + e0));
            if (g0) s0  = __ldg(p + e0 + 2);             // == p + i0 + 1
            if (f1) b0q = __ldg((const float2*)(p + e0 + WW));
            if (g1) s1  = __ldg(p + e0 + WW + 2);

            float v00 = par ? a0.y : a0.x;   // row y0, x0
            float v01 = par ? s0   : a0.y;   // row y0, x1
            float v10 = par ? b0q.y : b0q.x; // row y1, x0
            float v11 = par ? s1   : b0q.y;  // row y1, x1

            float v = w00 * v00 + w01 * v01 + w10 * v10 + w11 * v11;
            __stcs(ob + cc * (HH * WW) + 32 * k, v);
        }

        gx += sx;
        gy += sy;
    }
}

extern "C" void kernel_launch(void* const* d_in, const int* in_sizes, int n_in,
                              void* d_out, int out_size) {
    const float* x      = (const float*)d_in[0];
    const float* thetas = (const float*)d_in[1];
    const float* l1s    = (const float*)d_in[2];
    const float* l2s    = (const float*)d_in[3];
    float* out = (float*)d_out;

    dim3 block(32, 8, 1);
    dim3 grid(WW / (32 * PX), HH / 8, BB);   // 4 x 64 x 32 = 8192 CTAs
    warp_kernel<<<grid, block>>>(x, thetas, l1s, l2s, out);
}

// round 11
// speedup vs baseline: 1.4432x; 1.4432x over previous
#include <cuda_runtime.h>
#include <math.h>

// Problem constants: B=32, C=3, H=W=512
#define BB 32
#define CC 3
#define HH 512
#define WW 512
#define PX 4   // pixels per thread, warp-interleaved (stride 32)

// Fused single kernel, R8-proven body: warp-interleaved mapping, folded border
// masks, guarded scalar gathers, per-channel accumulate. Regs capped via
// launch_bounds to hold ~85% occupancy.
__global__ __launch_bounds__(256, 8) void warp_kernel(const float* __restrict__ x,
                                                      const float* __restrict__ thetas,
                                                      const float* __restrict__ l1s,
                                                      const float* __restrict__ l2s,
                                                      float* __restrict__ out) {
    int lane = threadIdx.x;                           // 0..31
    int py   = blockIdx.y * blockDim.y + threadIdx.y;
    int b    = blockIdx.z;
    int px0  = blockIdx.x * (32 * PX) + lane;

    // theta matrix (translation exactly zero); uniform within the CTA
    float th = -__ldg(thetas + b);
    float c, s;
    __sincosf(th, &s, &c);
    float il1 = 1.0f / __ldg(l1s + b);
    float il2 = 1.0f / __ldg(l2s + b);
    float m00 = c * c * il1 + s * s * il2;
    float m11 = s * s * il1 + c * c * il2;
    float m01 = c * s * (il2 - il1);

    float X = ((float)px0 + 0.5f) * (2.0f / (float)WW) - 1.0f;
    float Y = ((float)py + 0.5f) * (2.0f / (float)HH) - 1.0f;

    float gx = (m00 * X + m01 * Y + 1.0f) * ((float)WW * 0.5f) - 0.5f;
    float gy = (m01 * X + m11 * Y + 1.0f) * ((float)HH * 0.5f) - 0.5f;
    float sx = 32.0f * m00;
    float sy = 32.0f * m01;

    float w00[PX], w01[PX], w10[PX], w11[PX];
    int   i00[PX];

#pragma unroll
    for (int k = 0; k < PX; k++) {
        float x0f = floorf(gx);
        float y0f = floorf(gy);
        int x0 = (int)x0f;
        int y0 = (int)y0f;

        float wx1 = gx - x0f;
        float wx0 = 1.0f - wx1;
        float wy1 = gy - y0f;
        float wy0 = 1.0f - wy1;

        // fold border masks into the 1D weights (one unsigned compare each)
        float cx0 = ((unsigned)x0       < (unsigned)WW) ? wx0 : 0.0f;
        float cx1 = ((unsigned)(x0 + 1) < (unsigned)WW) ? wx1 : 0.0f;
        float cy0 = ((unsigned)y0       < (unsigned)HH) ? wy0 : 0.0f;
        float cy1 = ((unsigned)(y0 + 1) < (unsigned)HH) ? wy1 : 0.0f;

        w00[k] = cy0 * cx0;
        w01[k] = cy0 * cx1;
        w10[k] = cy1 * cx0;
        w11[k] = cy1 * cx1;

        i00[k] = y0 * WW + x0;   // raw index; loads are weight-guarded

        gx += sx;
        gy += sy;
    }

    const float* xb = x + (size_t)b * CC * HH * WW;
    float* ob = out + ((size_t)b * CC) * HH * WW + (size_t)py * WW + px0;

#pragma unroll
    for (int cc = 0; cc < CC; cc++) {
        const float* p = xb + (size_t)cc * HH * WW;
        float v[PX];
#pragma unroll
        for (int k = 0; k < PX; k++) {
            int i0 = i00[k];
            float acc = 0.0f;
            if (w00[k] != 0.0f) acc += w00[k] * __ldg(p + i0);
            if (w01[k] != 0.0f) acc += w01[k] * __ldg(p + i0 + 1);
            if (w10[k] != 0.0f) acc += w10[k] * __ldg(p + i0 + WW);
            if (w11[k] != 0.0f) acc += w11[k] * __ldg(p + i0 + WW + 1);
            v[k] = acc;
        }
        float* oc = ob + (size_t)cc * HH * WW;
#pragma unroll
        for (int k = 0; k < PX; k++)
            oc[32 * k] = v[k];
    }
}

extern "C" void kernel_launch(void* const* d_in, const int* in_sizes, int n_in,
                              void* d_out, int out_size) {
    const float* x      = (const float*)d_in[0];
    const float* thetas = (const float*)d_in[1];
    const float* l1s    = (const float*)d_in[2];
    const float* l2s    = (const float*)d_in[3];
    float* out = (float*)d_out;

    dim3 block(32, 8, 1);
    dim3 grid(WW / (32 * PX), HH / 8, BB);   // 4 x 64 x 32 = 8192 CTAs
    warp_kernel<<<grid, block>>>(x, thetas, l1s, l2s, out);
}

// round 12
// speedup vs baseline: 1.4624x; 1.0133x over previous
#include <cuda_runtime.h>
#include <math.h>

// Problem constants: B=32, C=3, H=W=512
#define BB 32
#define CC 3
#define HH 512
#define WW 512
#define PX 4   // pixels per thread, warp-interleaved (stride 32)

// Fused kernel: CTA-uniform fully-OOB skip (zero-fill fast path), then the
// R8-proven body: warp-interleaved mapping, folded border masks, guarded
// scalar gathers. Regs capped to hold ~85% occupancy.
__global__ __launch_bounds__(256, 8) void warp_kernel(const float* __restrict__ x,
                                                      const float* __restrict__ thetas,
                                                      const float* __restrict__ l1s,
                                                      const float* __restrict__ l2s,
                                                      float* __restrict__ out) {
    int lane    = threadIdx.x;                        // 0..31
    int b       = blockIdx.z;
    int px_base = blockIdx.x * (32 * PX);             // 128-px region in x
    int py_base = blockIdx.y * 8;                     // 8-row region in y
    int py      = py_base + threadIdx.y;
    int px0     = px_base + lane;

    // theta matrix (translation exactly zero); uniform within the CTA
    float th = -__ldg(thetas + b);
    float c, s;
    __sincosf(th, &s, &c);
    float il1 = 1.0f / __ldg(l1s + b);
    float il2 = 1.0f / __ldg(l2s + b);
    float m00 = c * c * il1 + s * s * il2;
    float m11 = s * s * il1 + c * c * il2;
    float m01 = c * s * (il2 - il1);

    // ---- CTA-uniform fully-OOB region test (gx,gy affine in px,py) ----
    {
        float Xlo = ((float)px_base + 0.5f)   * (2.0f / WW) - 1.0f;
        float Xhi = ((float)px_base + 127.5f) * (2.0f / WW) - 1.0f;
        float Ylo = ((float)py_base + 0.5f)   * (2.0f / HH) - 1.0f;
        float Yhi = ((float)py_base + 7.5f)   * (2.0f / HH) - 1.0f;

        // gx = (m00*X + m01*Y + 1)*W/2 - 0.5 ; m00 > 0 so X-extremes at Xlo/Xhi
        float ax_lo = fminf(m01 * Ylo, m01 * Yhi);
        float ax_hi = fmaxf(m01 * Ylo, m01 * Yhi);
        float gx_min = (m00 * Xlo + ax_lo + 1.0f) * (WW * 0.5f) - 0.5f;
        float gx_max = (m00 * Xhi + ax_hi + 1.0f) * (WW * 0.5f) - 0.5f;

        // gy = (m01*X + m11*Y + 1)*H/2 - 0.5 ; m11 > 0 so Y-extremes at Ylo/Yhi
        float ay_lo = fminf(m01 * Xlo, m01 * Xhi);
        float ay_hi = fmaxf(m01 * Xlo, m01 * Xhi);
        float gy_min = (m11 * Ylo + ay_lo + 1.0f) * (HH * 0.5f) - 0.5f;
        float gy_max = (m11 * Yhi + ay_hi + 1.0f) * (HH * 0.5f) - 0.5f;

        const float MARGIN = 1e-3f;
        bool dead = (gx_max < -1.0f - MARGIN) | (gx_min >= (float)WW + MARGIN) |
                    (gy_max < -1.0f - MARGIN) | (gy_min >= (float)HH + MARGIN);
        if (dead) {   // uniform across the CTA — no divergence
            float4 z = make_float4(0.f, 0.f, 0.f, 0.f);
            int t = threadIdx.y * 32 + lane;          // 0..255
            // 3 ch x 8 rows x 32 float4 = 768 float4 slots
#pragma unroll
            for (int i = 0; i < 3; i++) {
                int slot = t + i * 256;
                int cc = slot >> 8;                    // channel
                int r  = (slot >> 5) & 7;              // row in region
                int q  = slot & 31;                    // float4 within row
                float4* dst = (float4*)(out + ((size_t)b * CC + cc) * HH * WW +
                                        (size_t)(py_base + r) * WW + px_base) + q;
                __stcs(dst, z);
            }
            return;
        }
    }

    float X = ((float)px0 + 0.5f) * (2.0f / (float)WW) - 1.0f;
    float Y = ((float)py + 0.5f) * (2.0f / (float)HH) - 1.0f;

    float gx = (m00 * X + m01 * Y + 1.0f) * ((float)WW * 0.5f) - 0.5f;
    float gy = (m01 * X + m11 * Y + 1.0f) * ((float)HH * 0.5f) - 0.5f;
    float sx = 32.0f * m00;
    float sy = 32.0f * m01;

    float w00[PX], w01[PX], w10[PX], w11[PX];
    int   i00[PX];

#pragma unroll
    for (int k = 0; k < PX; k++) {
        float x0f = floorf(gx);
        float y0f = floorf(gy);
        int x0 = (int)x0f;
        int y0 = (int)y0f;

        float wx1 = gx - x0f;
        float wx0 = 1.0f - wx1;
        float wy1 = gy - y0f;
        float wy0 = 1.0f - wy1;

        // fold border masks into the 1D weights (one unsigned compare each)
        float cx0 = ((unsigned)x0       < (unsigned)WW) ? wx0 : 0.0f;
        float cx1 = ((unsigned)(x0 + 1) < (unsigned)WW) ? wx1 : 0.0f;
        float cy0 = ((unsigned)y0       < (unsigned)HH) ? wy0 : 0.0f;
        float cy1 = ((unsigned)(y0 + 1) < (unsigned)HH) ? wy1 : 0.0f;

        w00[k] = cy0 * cx0;
        w01[k] = cy0 * cx1;
        w10[k] = cy1 * cx0;
        w11[k] = cy1 * cx1;

        i00[k] = y0 * WW + x0;   // raw index; loads are weight-guarded

        gx += sx;
        gy += sy;
    }

    const float* xb = x + (size_t)b * CC * HH * WW;
    float* ob = out + ((size_t)b * CC) * HH * WW + (size_t)py * WW + px0;

#pragma unroll
    for (int cc = 0; cc < CC; cc++) {
        const float* p = xb + (size_t)cc * HH * WW;
        float v[PX];
#pragma unroll
        for (int k = 0; k < PX; k++) {
            int i0 = i00[k];
            float acc = 0.0f;
            if (w00[k] != 0.0f) acc += w00[k] * __ldg(p + i0);
            if (w01[k] != 0.0f) acc += w01[k] * __ldg(p + i0 + 1);
            if (w10[k] != 0.0f) acc += w10[k] * __ldg(p + i0 + WW);
            if (w11[k] != 0.0f) acc += w11[k] * __ldg(p + i0 + WW + 1);
            v[k] = acc;
        }
        float* oc = ob + (size_t)cc * HH * WW;
#pragma unroll
        for (int k = 0; k < PX; k++)
            oc[32 * k] = v[k];
    }
}

extern "C" void kernel_launch(void* const* d_in, const int* in_sizes, int n_in,
                              void* d_out, int out_size) {
    const float* x      = (const float*)d_in[0];
    const float* thetas = (const float*)d_in[1];
    const float* l1s    = (const float*)d_in[2];
    const float* l2s    = (const float*)d_in[3];
    float* out = (float*)d_out;

    dim3 block(32, 8, 1);
    dim3 grid(WW / (32 * PX), HH / 8, BB);   // 4 x 64 x 32 = 8192 CTAs
    warp_kernel<<<grid, block>>>(x, thetas, l1s, l2s, out);
}

// round 13
// speedup vs baseline: 1.5170x; 1.0373x over previous
#include <cuda_runtime.h>
#include <math.h>

// Problem constants: B=32, C=3, H=W=512
#define BB 32
#define CC 3
#define HH 512
#define WW 512
#define PX 4   // pixels per thread, warp-interleaved (stride 32)

// Fused kernel with WARP-uniform fully-OOB skip: each warp owns a 128-px row
// segment; gx/gy are affine and monotone in X, so two endpoint evaluations
// bound the whole segment. Uniform branch => no intra-warp divergence.
// Main body: R8-proven warp-interleaved guarded gathers, regs capped.
__global__ __launch_bounds__(256, 8) void warp_kernel(const float* __restrict__ x,
                                                      const float* __restrict__ thetas,
                                                      const float* __restrict__ l1s,
                                                      const float* __restrict__ l2s,
                                                      float* __restrict__ out) {
    int lane    = threadIdx.x;                        // 0..31
    int b       = blockIdx.z;
    int px_base = blockIdx.x * (32 * PX);             // 128-px segment in x
    int py      = blockIdx.y * 8 + threadIdx.y;       // this warp's row
    int px0     = px_base + lane;

    // theta matrix (translation exactly zero); uniform within the CTA
    float th = -__ldg(thetas + b);
    float c, s;
    __sincosf(th, &s, &c);
    float il1 = 1.0f / __ldg(l1s + b);
    float il2 = 1.0f / __ldg(l2s + b);
    float m00 = c * c * il1 + s * s * il2;
    float m11 = s * s * il1 + c * c * il2;
    float m01 = c * s * (il2 - il1);

    float Y = ((float)py + 0.5f) * (2.0f / (float)HH) - 1.0f;

    // ---- warp-uniform fully-OOB segment test (endpoints in X) ----
    {
        float Xlo = ((float)px_base + 0.5f)   * (2.0f / WW) - 1.0f;
        float Xhi = ((float)px_base + 127.5f) * (2.0f / WW) - 1.0f;

        // gx monotone increasing in X (m00 > 0)
        float gx_lo = (m00 * Xlo + m01 * Y + 1.0f) * (WW * 0.5f) - 0.5f;
        float gx_hi = (m00 * Xhi + m01 * Y + 1.0f) * (WW * 0.5f) - 0.5f;
        // gy monotone in X with slope sign(m01)
        float gyA = (m01 * Xlo + m11 * Y + 1.0f) * (HH * 0.5f) - 0.5f;
        float gyB = (m01 * Xhi + m11 * Y + 1.0f) * (HH * 0.5f) - 0.5f;
        float gy_lo = fminf(gyA, gyB);
        float gy_hi = fmaxf(gyA, gyB);

        const float MARGIN = 1e-3f;
        bool dead = (gx_hi < -1.0f - MARGIN) | (gx_lo >= (float)WW + MARGIN) |
                    (gy_hi < -1.0f - MARGIN) | (gy_lo >= (float)HH + MARGIN);
        if (dead) {   // uniform across the warp — no divergence
            float4 z = make_float4(0.f, 0.f, 0.f, 0.f);
            float4* dst = (float4*)(out + ((size_t)b * CC) * HH * WW +
                                    (size_t)py * WW + px_base) + lane;
#pragma unroll
            for (int cc = 0; cc < CC; cc++)
                __stcs(dst + cc * (HH * WW / 4), z);
            return;
        }
    }

    float X = ((float)px0 + 0.5f) * (2.0f / (float)WW) - 1.0f;

    float gx = (m00 * X + m01 * Y + 1.0f) * ((float)WW * 0.5f) - 0.5f;
    float gy = (m01 * X + m11 * Y + 1.0f) * ((float)HH * 0.5f) - 0.5f;
    float sx = 32.0f * m00;
    float sy = 32.0f * m01;

    float w00[PX], w01[PX], w10[PX], w11[PX];
    int   i00[PX];

#pragma unroll
    for (int k = 0; k < PX; k++) {
        float x0f = floorf(gx);
        float y0f = floorf(gy);
        int x0 = (int)x0f;
        int y0 = (int)y0f;

        float wx1 = gx - x0f;
        float wx0 = 1.0f - wx1;
        float wy1 = gy - y0f;
        float wy0 = 1.0f - wy1;

        // fold border masks into the 1D weights (one unsigned compare each)
        float cx0 = ((unsigned)x0       < (unsigned)WW) ? wx0 : 0.0f;
        float cx1 = ((unsigned)(x0 + 1) < (unsigned)WW) ? wx1 : 0.0f;
        float cy0 = ((unsigned)y0       < (unsigned)HH) ? wy0 : 0.0f;
        float cy1 = ((unsigned)(y0 + 1) < (unsigned)HH) ? wy1 : 0.0f;

        w00[k] = cy0 * cx0;
        w01[k] = cy0 * cx1;
        w10[k] = cy1 * cx0;
        w11[k] = cy1 * cx1;

        i00[k] = y0 * WW + x0;   // raw index; loads are weight-guarded

        gx += sx;
        gy += sy;
    }

    const float* xb = x + (size_t)b * CC * HH * WW;
    float* ob = out + ((size_t)b * CC) * HH * WW + (size_t)py * WW + px0;

#pragma unroll
    for (int cc = 0; cc < CC; cc++) {
        const float* p = xb + (size_t)cc * HH * WW;
        float v[PX];
#pragma unroll
        for (int k = 0; k < PX; k++) {
            int i0 = i00[k];
            float acc = 0.0f;
            if (w00[k] != 0.0f) acc += w00[k] * __ldg(p + i0);
            if (w01[k] != 0.0f) acc += w01[k] * __ldg(p + i0 + 1);
            if (w10[k] != 0.0f) acc += w10[k] * __ldg(p + i0 + WW);
            if (w11[k] != 0.0f) acc += w11[k] * __ldg(p + i0 + WW + 1);
            v[k] = acc;
        }
        float* oc = ob + (size_t)cc * HH * WW;
#pragma unroll
        for (int k = 0; k < PX; k++)
            oc[32 * k] = v[k];
    }
}

extern "C" void kernel_launch(void* const* d_in, const int* in_sizes, int n_in,
                              void* d_out, int out_size) {
    const float* x      = (const float*)d_in[0];
    const float* thetas = (const float*)d_in[1];
    const float* l1s    = (const float*)d_in[2];
    const float* l2s    = (const float*)d_in[3];
    float* out = (float*)d_out;

    dim3 block(32, 8, 1);
    dim3 grid(WW / (32 * PX), HH / 8, BB);   // 4 x 64 x 32 = 8192 CTAs
    warp_kernel<<<grid, block>>>(x, thetas, l1s, l2s, out);
}